// round 14
// baseline (speedup 1.0000x reference)
#include <cuda_runtime.h>
#include <cuda_bf16.h>
#include <math.h>

#define NN   50000
#define FIN  128
#define HIDD 256
#define NHD  4
#define DH   64
#define NE   400000
#define CATF 384
#define TTYP 2
#define KWMAX (CATF/2)
#define PKW   (CATF/2)
#define NSLOT 6
#define SCB   196

// ---------------- per-type scratch (device globals) ------------------------
static __device__ float g_z  [TTYP][(size_t)NN*HIDD];
static __device__ float g_h  [TTYP][(size_t)NN*HIDD];
static __device__ float g_el [TTYP][NN*NHD];
static __device__ float g_er [TTYP][NN*NHD];
static __device__ float g_stats[TTYP][2*HIDD];
static __device__ float g_scale[TTYP][HIDD];
static __device__ float g_shift[TTYP][HIDD];
static __device__ unsigned int g_wh[TTYP][NSLOT][HIDD*KWMAX];
static __device__ unsigned int g_wl[TTYP][NSLOT][HIDD*KWMAX];
static __device__ unsigned int g_pah[TTYP][(size_t)NN*PKW];
static __device__ unsigned int g_pal[TTYP][(size_t)NN*PKW];
static __device__ unsigned int g_fh[(size_t)NN*(FIN/2)];
static __device__ unsigned int g_fl[(size_t)NN*(FIN/2)];
// CSR
static __device__ int g_cnt[TTYP][NN];
static __device__ int g_rowptr[TTYP][NN+1];
static __device__ int g_cur[TTYP][NN];
static __device__ int g_csrc[TTYP][NE];
static __device__ int g_bsum[TTYP][SCB];
static __device__ int g_boff[TTYP][SCB];

#define SSTR 20
#define AFSTR 36
#define GEMM_SMEM (2 * 4 * 128 * SSTR * 4)
#define GEMM_AFF_SMEM (2*128*AFSTR*4 + 2*128*SSTR*4 + 2*2*128*SSTR*4)

__global__ void gemm_tc_kernel(const unsigned int*, const unsigned int*,
                               const unsigned int*, const unsigned int*,
                               const float*, float*, float*,
                               const float*, const float*, float*, float*,
                               int, int, int, int, int);
__global__ void gemm_aff_kernel(const float*, const float*, const float*,
                                const unsigned int*, const unsigned int*,
                                const float*, float*, int, int, int, int);

// ---------------- streams/events (created once, statically) ----------------
namespace {
struct SI {
    cudaStream_t s[TTYP], s2[TTYP];
    cudaEvent_t e0, e1, e2, eC[TTYP];
    SI() {
        for (int t = 0; t < TTYP; t++) {
            cudaStreamCreateWithFlags(&s[t], cudaStreamNonBlocking);
            cudaStreamCreateWithFlags(&s2[t], cudaStreamNonBlocking);
            cudaEventCreateWithFlags(&eC[t], cudaEventDisableTiming);
        }
        cudaEventCreateWithFlags(&e0, cudaEventDisableTiming);
        cudaEventCreateWithFlags(&e1, cudaEventDisableTiming);
        cudaEventCreateWithFlags(&e2, cudaEventDisableTiming);
        cudaFuncSetAttribute(gemm_tc_kernel,
                             cudaFuncAttributeMaxDynamicSharedMemorySize, GEMM_SMEM);
        cudaFuncSetAttribute(gemm_aff_kernel,
                             cudaFuncAttributeMaxDynamicSharedMemorySize, GEMM_AFF_SMEM);
    }
};
SI g_si;
}

// ---------------- helpers --------------------------------------------------
__device__ __forceinline__ float lrelu(float v) { return v >= 0.f ? v : 0.2f * v; }

__device__ __forceinline__ unsigned int pack2(__nv_bfloat16 a, __nv_bfloat16 b) {
    return (unsigned int)__bfloat16_as_ushort(a) |
           ((unsigned int)__bfloat16_as_ushort(b) << 16);
}

__device__ __forceinline__ void split_bf(float v, __nv_bfloat16& h, __nv_bfloat16& l) {
    h = __float2bfloat16_rn(v);
    l = __float2bfloat16_rn(v - __bfloat162float(h));
}

__device__ __forceinline__ void split4(float4 v, unsigned int* hp, unsigned int* lp) {
    __nv_bfloat16 h0, h1, h2, h3, l0, l1, l2, l3;
    split_bf(v.x, h0, l0); split_bf(v.y, h1, l1);
    split_bf(v.z, h2, l2); split_bf(v.w, h3, l3);
    hp[0] = pack2(h0, h1); hp[1] = pack2(h2, h3);
    lp[0] = pack2(l0, l1); lp[1] = pack2(l2, l3);
}

__device__ __forceinline__ void mma16816(float* c, const unsigned int* a, const unsigned int* b) {
    asm volatile(
        "mma.sync.aligned.m16n8k16.row.col.f32.bf16.bf16.f32 "
        "{%0,%1,%2,%3}, {%4,%5,%6,%7}, {%8,%9}, {%0,%1,%2,%3};"
        : "+f"(c[0]), "+f"(c[1]), "+f"(c[2]), "+f"(c[3])
        : "r"(a[0]), "r"(a[1]), "r"(a[2]), "r"(a[3]), "r"(b[0]), "r"(b[1]));
}

__device__ __forceinline__ void cp16(void* dst, const void* src, int sz) {
    unsigned int d = (unsigned int)__cvta_generic_to_shared(dst);
    asm volatile("cp.async.cg.shared.global [%0], [%1], 16, %2;"
                 :: "r"(d), "l"(src), "r"(sz) : "memory");
}
__device__ __forceinline__ void cp_commit() {
    asm volatile("cp.async.commit_group;" ::: "memory");
}
template <int N>
__device__ __forceinline__ void cp_wait() {
    asm volatile("cp.async.wait_group %0;" :: "n"(N) : "memory");
}

// ---------------- CSR build -------------------------------------------------
__global__ void zero_int_kernel(int* __restrict__ p, int n) {
    int i = blockIdx.x * blockDim.x + threadIdx.x;
    if (i < n) p[i] = 0;
}

__global__ void count_kernel(const int* __restrict__ dst, int* __restrict__ cnt) {
    int e = blockIdx.x * blockDim.x + threadIdx.x;
    if (e < NE) atomicAdd(&cnt[dst[e]], 1);
}

__global__ void scan1_kernel(const int* __restrict__ cnt, int* __restrict__ bsum) {
    __shared__ int sh[256];
    int i = blockIdx.x * 256 + threadIdx.x;
    sh[threadIdx.x] = (i < NN) ? cnt[i] : 0;
    __syncthreads();
    for (int off = 128; off; off >>= 1) {
        if (threadIdx.x < off) sh[threadIdx.x] += sh[threadIdx.x + off];
        __syncthreads();
    }
    if (threadIdx.x == 0) bsum[blockIdx.x] = sh[0];
}

__global__ void scan2_kernel(const int* __restrict__ bsum, int* __restrict__ boff,
                             int* __restrict__ rowptr) {
    __shared__ int sh[256];
    int tid = threadIdx.x;
    int v = (tid < SCB) ? bsum[tid] : 0;
    sh[tid] = v;
    __syncthreads();
    for (int off = 1; off < 256; off <<= 1) {
        int u = (tid >= off) ? sh[tid - off] : 0;
        __syncthreads();
        sh[tid] += u;
        __syncthreads();
    }
    if (tid < SCB) boff[tid] = sh[tid] - v;
    if (tid == SCB - 1) rowptr[NN] = sh[tid];
}

__global__ void scan3_kernel(const int* __restrict__ cnt, const int* __restrict__ boff,
                             int* __restrict__ rowptr, int* __restrict__ cur) {
    __shared__ int sh[256];
    int tid = threadIdx.x;
    int i = blockIdx.x * 256 + tid;
    int v = (i < NN) ? cnt[i] : 0;
    sh[tid] = v;
    __syncthreads();
    for (int off = 1; off < 256; off <<= 1) {
        int u = (tid >= off) ? sh[tid - off] : 0;
        __syncthreads();
        sh[tid] += u;
        __syncthreads();
    }
    if (i < NN) {
        int r = boff[blockIdx.x] + sh[tid] - v;
        rowptr[i] = r;
        cur[i] = r;
    }
}

__global__ void fill_kernel(const int* __restrict__ src, const int* __restrict__ dst,
                            int* __restrict__ cur, int* __restrict__ csrc) {
    int e = blockIdx.x * blockDim.x + threadIdx.x;
    if (e >= NE) return;
    int pos = atomicAdd(&cur[dst[e]], 1);
    csrc[pos] = src[e];
}

// ---------------- converters ------------------------------------------------
__global__ void aconv_kernel(const float* __restrict__ A, unsigned int* __restrict__ H,
                             unsigned int* __restrict__ L, int n4) {
    int idx = blockIdx.x * blockDim.x + threadIdx.x;
    if (idx >= n4) return;
    float4 v = *(const float4*)(A + (size_t)idx * 4);
    unsigned int hp[2], lp[2];
    split4(v, hp, lp);
    *(uint2*)(H + (size_t)idx * 2) = make_uint2(hp[0], hp[1]);
    *(uint2*)(L + (size_t)idx * 2) = make_uint2(lp[0], lp[1]);
}

__global__ void wconv_kernel(const float* __restrict__ W, int K,
                             unsigned int* __restrict__ wh, unsigned int* __restrict__ wl) {
    int idx = blockIdx.x * blockDim.x + threadIdx.x;
    int Kw = K / 2;
    if (idx >= HIDD * Kw) return;
    int kp = idx / HIDD;
    int n = idx - kp * HIDD;
    float v0 = W[(size_t)(2 * kp) * HIDD + n];
    float v1 = W[(size_t)(2 * kp + 1) * HIDD + n];
    __nv_bfloat16 h0, h1, l0, l1;
    split_bf(v0, h0, l0); split_bf(v1, h1, l1);
    wh[(size_t)n * Kw + kp] = pack2(h0, h1);
    wl[(size_t)n * Kw + kp] = pack2(l0, l1);
}

__global__ void zero2_kernel(float* __restrict__ a, float* __restrict__ b, int n) {
    int i4 = (blockIdx.x * blockDim.x + threadIdx.x) * 4;
    if (i4 >= n) return;
    *(float4*)(a + i4) = make_float4(0.f, 0.f, 0.f, 0.f);
    *(float4*)(b + i4) = make_float4(0.f, 0.f, 0.f, 0.f);
}

// ---------------- tensor-core GEMM (packed A), fused BN-stats / el-er -------
__global__ __launch_bounds__(256, 2)
void gemm_tc_kernel(const unsigned int* __restrict__ AHg, const unsigned int* __restrict__ ALg,
                    const unsigned int* __restrict__ BHg, const unsigned int* __restrict__ BLg,
                    const float* __restrict__ bias, float* __restrict__ C,
                    float* __restrict__ stats,
                    const float* __restrict__ alv, const float* __restrict__ arv,
                    float* __restrict__ elp, float* __restrict__ erp,
                    int M, int Kw, int ldc, int coff, int relu_flag) {
    extern __shared__ unsigned int smem[];
    const int BUF = 128 * SSTR;
    unsigned int* AH = smem;
    unsigned int* AL = AH + 2 * BUF;
    unsigned int* BH = AL + 2 * BUF;
    unsigned int* BL = BH + 2 * BUF;

    int tid = threadIdx.x;
    int lane = tid & 31, wid = tid >> 5;
    int lm = lane >> 2, lc = lane & 3;
    int m0 = (wid >> 2) * 64;
    int n0w = (wid & 3) * 32;
    int rowBase = blockIdx.y * 128;
    int colBase = blockIdx.x * 128;

    float acc[16][4];
#pragma unroll
    for (int i = 0; i < 16; i++)
#pragma unroll
        for (int j = 0; j < 4; j++) acc[i][j] = 0.f;

    int nkt = Kw / 16;

    auto stage = [&](int sidx, int kt) {
        int k0w = kt * 16;
        int off = sidx * BUF;
#pragma unroll
        for (int i = 0; i < 2; i++) {
            int p = tid + i * 256;
            int m = p >> 2;
            int cc = (p & 3) * 4;
            int row = rowBase + m;
            int sz = (row < M) ? 16 : 0;
            cp16(&AH[off + m * SSTR + cc], AHg + (size_t)row * Kw + k0w + cc, sz);
            cp16(&AL[off + m * SSTR + cc], ALg + (size_t)row * Kw + k0w + cc, sz);
            int n = colBase + m;
            cp16(&BH[off + m * SSTR + cc], BHg + (size_t)n * Kw + k0w + cc, 16);
            cp16(&BL[off + m * SSTR + cc], BLg + (size_t)n * Kw + k0w + cc, 16);
        }
        cp_commit();
    };

    stage(0, 0);

    for (int kt = 0; kt < nkt; kt++) {
        int cur = kt & 1;
        if (kt + 1 < nkt) {
            stage(cur ^ 1, kt + 1);
            cp_wait<1>();
        } else {
            cp_wait<0>();
        }
        __syncthreads();
        int off = cur * BUF;
#pragma unroll
        for (int kk = 0; kk < 2; kk++) {
            int kw = kk * 8;
            unsigned int ah[4][4], al[4][4], bh[4][2], bl[4][2];
#pragma unroll
            for (int mi = 0; mi < 4; mi++) {
                int r = m0 + mi * 16 + lm;
                int w0 = off + r * SSTR + kw + lc;
                int w1 = off + (r + 8) * SSTR + kw + lc;
                ah[mi][0] = AH[w0]; ah[mi][1] = AH[w1];
                ah[mi][2] = AH[w0 + 4]; ah[mi][3] = AH[w1 + 4];
                al[mi][0] = AL[w0]; al[mi][1] = AL[w1];
                al[mi][2] = AL[w0 + 4]; al[mi][3] = AL[w1 + 4];
            }
#pragma unroll
            for (int ni = 0; ni < 4; ni++) {
                int n = n0w + ni * 8 + lm;
                int w0 = off + n * SSTR + kw + lc;
                bh[ni][0] = BH[w0]; bh[ni][1] = BH[w0 + 4];
                bl[ni][0] = BL[w0]; bl[ni][1] = BL[w0 + 4];
            }
#pragma unroll
            for (int mi = 0; mi < 4; mi++)
#pragma unroll
                for (int ni = 0; ni < 4; ni++) {
                    float* c = acc[mi * 4 + ni];
                    mma16816(c, ah[mi], bh[ni]);
                    mma16816(c, ah[mi], bl[ni]);
                    mma16816(c, al[mi], bh[ni]);
                }
        }
        __syncthreads();
    }

    float cs[8] = {0.f,0.f,0.f,0.f,0.f,0.f,0.f,0.f};
    float cq[8] = {0.f,0.f,0.f,0.f,0.f,0.f,0.f,0.f};
    float pel[8] = {0.f,0.f,0.f,0.f,0.f,0.f,0.f,0.f};
    float per[8] = {0.f,0.f,0.f,0.f,0.f,0.f,0.f,0.f};
#pragma unroll
    for (int mi = 0; mi < 4; mi++) {
#pragma unroll
        for (int ni = 0; ni < 4; ni++) {
            float* c = acc[mi * 4 + ni];
            int r0 = rowBase + m0 + mi * 16 + lm;
            int r1 = r0 + 8;
            int col = colBase + n0w + ni * 8 + lc * 2;
            float b0 = bias ? bias[col] : 0.f;
            float b1 = bias ? bias[col + 1] : 0.f;
            float v0 = c[0] + b0, v1 = c[1] + b1;
            float v2 = c[2] + b0, v3 = c[3] + b1;
            if (relu_flag) {
                v0 = fmaxf(v0, 0.f); v1 = fmaxf(v1, 0.f);
                v2 = fmaxf(v2, 0.f); v3 = fmaxf(v3, 0.f);
            }
            if (r0 < M) *(float2*)(C + (size_t)r0 * ldc + coff + col) = make_float2(v0, v1);
            if (r1 < M) *(float2*)(C + (size_t)r1 * ldc + coff + col) = make_float2(v2, v3);
            if (stats) {
                if (r0 < M) { cs[ni*2] += v0; cq[ni*2] += v0*v0;
                              cs[ni*2+1] += v1; cq[ni*2+1] += v1*v1; }
                if (r1 < M) { cs[ni*2] += v2; cq[ni*2] += v2*v2;
                              cs[ni*2+1] += v3; cq[ni*2+1] += v3*v3; }
            }
            if (elp) {
                float2 av = *(const float2*)(alv + col);
                float2 bv = *(const float2*)(arv + col);
                pel[mi*2]   += v0 * av.x + v1 * av.y;
                per[mi*2]   += v0 * bv.x + v1 * bv.y;
                pel[mi*2+1] += v2 * av.x + v3 * av.y;
                per[mi*2+1] += v2 * bv.x + v3 * bv.y;
            }
        }
    }
    if (stats) {
#pragma unroll
        for (int j = 0; j < 8; j++) {
#pragma unroll
            for (int off = 4; off < 32; off <<= 1) {
                cs[j] += __shfl_xor_sync(0xffffffffu, cs[j], off);
                cq[j] += __shfl_xor_sync(0xffffffffu, cq[j], off);
            }
        }
        if (lm == 0) {
#pragma unroll
            for (int j = 0; j < 8; j++) {
                int col = colBase + n0w + (j >> 1) * 8 + lc * 2 + (j & 1);
                atomicAdd(&stats[col], cs[j]);
                atomicAdd(&stats[HIDD + col], cq[j]);
            }
        }
    }
    if (elp) {
#pragma unroll
        for (int j = 0; j < 8; j++) {
            pel[j] += __shfl_xor_sync(0xffffffffu, pel[j], 1);
            pel[j] += __shfl_xor_sync(0xffffffffu, pel[j], 2);
            per[j] += __shfl_xor_sync(0xffffffffu, per[j], 1);
            per[j] += __shfl_xor_sync(0xffffffffu, per[j], 2);
        }
        if (lc == 0) {
            int head = (colBase + n0w) >> 6;
#pragma unroll
            for (int mi = 0; mi < 4; mi++) {
                int r0 = rowBase + m0 + mi * 16 + lm;
                int r1 = r0 + 8;
                if (r0 < M) {
                    atomicAdd(&elp[r0 * NHD + head], pel[mi*2]);
                    atomicAdd(&erp[r0 * NHD + head], per[mi*2]);
                }
                if (r1 < M) {
                    atomicAdd(&elp[r1 * NHD + head], pel[mi*2+1]);
                    atomicAdd(&erp[r1 * NHD + head], per[mi*2+1]);
                }
            }
        }
    }
}

// ---------------- affine GEMM: A = relu(z*scale[k]+shift[k]) ----------------
__global__ __launch_bounds__(256, 2)
void gemm_aff_kernel(const float* __restrict__ Ag, const float* __restrict__ scale,
                     const float* __restrict__ shift,
                     const unsigned int* __restrict__ BHg, const unsigned int* __restrict__ BLg,
                     const float* __restrict__ bias, float* __restrict__ C,
                     int M, int Kw, int ldc, int coff) {
    extern __shared__ unsigned int smem[];
    const int BUF = 128 * SSTR;
    const int ABUFA = 128 * AFSTR;
    float* AsF = (float*)smem;
    unsigned int* AH = smem + 2 * ABUFA;
    unsigned int* AL = AH + BUF;
    unsigned int* BH = AL + BUF;
    unsigned int* BL = BH + 2 * BUF;

    int tid = threadIdx.x;
    int lane = tid & 31, wid = tid >> 5;
    int lm = lane >> 2, lc = lane & 3;
    int m0 = (wid >> 2) * 64;
    int n0w = (wid & 3) * 32;
    int rowBase = blockIdx.y * 128;
    int colBase = blockIdx.x * 128;
    int K = Kw * 2;

    float acc[16][4];
#pragma unroll
    for (int i = 0; i < 16; i++)
#pragma unroll
        for (int j = 0; j < 4; j++) acc[i][j] = 0.f;

    int nkt = Kw / 16;

    auto stage = [&](int sidx, int kt) {
        int k0 = kt * 32;
        int k0w = kt * 16;
        int offF = sidx * ABUFA;
#pragma unroll
        for (int i = 0; i < 4; i++) {
            int p = tid + i * 256;
            int m = p >> 3;
            int k4 = (p & 7) * 4;
            int row = rowBase + m;
            int sz = (row < M) ? 16 : 0;
            cp16(&AsF[offF + m * AFSTR + k4], Ag + (size_t)row * K + k0 + k4, sz);
        }
        int offB = sidx * BUF;
#pragma unroll
        for (int i = 0; i < 2; i++) {
            int p = tid + i * 256;
            int n = p >> 2;
            int cc = (p & 3) * 4;
            cp16(&BH[offB + n * SSTR + cc], BHg + (size_t)(colBase + n) * Kw + k0w + cc, 16);
            cp16(&BL[offB + n * SSTR + cc], BLg + (size_t)(colBase + n) * Kw + k0w + cc, 16);
        }
        cp_commit();
    };

    stage(0, 0);

    for (int kt = 0; kt < nkt; kt++) {
        int cur = kt & 1;
        if (kt + 1 < nkt) {
            stage(cur ^ 1, kt + 1);
            cp_wait<1>();
        } else {
            cp_wait<0>();
        }
        __syncthreads();
        {
            int offF = cur * ABUFA;
#pragma unroll
            for (int i = 0; i < 4; i++) {
                int p = tid + i * 256;
                int m = p >> 3;
                int k4 = (p & 7) * 4;
                float4 v = *(float4*)&AsF[offF + m * AFSTR + k4];
                int kg = kt * 32 + k4;
                float4 sc = *(const float4*)(scale + kg);
                float4 sh = *(const float4*)(shift + kg);
                v.x = fmaxf(v.x * sc.x + sh.x, 0.f);
                v.y = fmaxf(v.y * sc.y + sh.y, 0.f);
                v.z = fmaxf(v.z * sc.z + sh.z, 0.f);
                v.w = fmaxf(v.w * sc.w + sh.w, 0.f);
                unsigned int hp[2], lp[2];
                split4(v, hp, lp);
                int w = m * SSTR + (k4 >> 1);
                AH[w] = hp[0]; AH[w + 1] = hp[1];
                AL[w] = lp[0]; AL[w + 1] = lp[1];
            }
        }
        __syncthreads();
        int offB = cur * BUF;
#pragma unroll
        for (int kk = 0; kk < 2; kk++) {
            int kw = kk * 8;
            unsigned int ah[4][4], al[4][4], bh[4][2], bl[4][2];
#pragma unroll
            for (int mi = 0; mi < 4; mi++) {
                int r = m0 + mi * 16 + lm;
                int w0 = r * SSTR + kw + lc;
                int w1 = (r + 8) * SSTR + kw + lc;
                ah[mi][0] = AH[w0]; ah[mi][1] = AH[w1];
                ah[mi][2] = AH[w0 + 4]; ah[mi][3] = AH[w1 + 4];
                al[mi][0] = AL[w0]; al[mi][1] = AL[w1];
                al[mi][2] = AL[w0 + 4]; al[mi][3] = AL[w1 + 4];
            }
#pragma unroll
            for (int ni = 0; ni < 4; ni++) {
                int n = n0w + ni * 8 + lm;
                int w0 = offB + n * SSTR + kw + lc;
                bh[ni][0] = BH[w0]; bh[ni][1] = BH[w0 + 4];
                bl[ni][0] = BL[w0]; bl[ni][1] = BL[w0 + 4];
            }
#pragma unroll
            for (int mi = 0; mi < 4; mi++)
#pragma unroll
                for (int ni = 0; ni < 4; ni++) {
                    float* c = acc[mi * 4 + ni];
                    mma16816(c, ah[mi], bh[ni]);
                    mma16816(c, ah[mi], bl[ni]);
                    mma16816(c, al[mi], bh[ni]);
                }
        }
        __syncthreads();
    }

#pragma unroll
    for (int mi = 0; mi < 4; mi++) {
#pragma unroll
        for (int ni = 0; ni < 4; ni++) {
            float* c = acc[mi * 4 + ni];
            int r0 = rowBase + m0 + mi * 16 + lm;
            int r1 = r0 + 8;
            int col = colBase + n0w + ni * 8 + lc * 2;
            float b0 = bias[col], b1 = bias[col + 1];
            float v0 = fmaxf(c[0] + b0, 0.f), v1 = fmaxf(c[1] + b1, 0.f);
            float v2 = fmaxf(c[2] + b0, 0.f), v3 = fmaxf(c[3] + b1, 0.f);
            if (r0 < M) *(float2*)(C + (size_t)r0 * ldc + coff + col) = make_float2(v0, v1);
            if (r1 < M) *(float2*)(C + (size_t)r1 * ldc + coff + col) = make_float2(v2, v3);
        }
    }
}

// ---------------- fused GAT gather (single pass, 2-way unrolled) ------------
template <int PACKED>
__global__ __launch_bounds__(256)
void gat_gather_kernel(const int* __restrict__ csrc, const int* __restrict__ rowptr,
                       const float* __restrict__ elp, const float* __restrict__ erp,
                       const float* __restrict__ z, const float* __restrict__ bias,
                       float* __restrict__ hout,
                       unsigned int* __restrict__ pah, unsigned int* __restrict__ pal) {
    int warp = (blockIdx.x * blockDim.x + threadIdx.x) >> 5;
    if (warp >= NN) return;
    int lane = threadIdx.x & 31;
    int head = lane >> 3;
    int beg = rowptr[warp], end = rowptr[warp + 1];
    float erh = erp[warp * NHD + head];

    float den = 0.f;
    float msg[8] = {0.f, 0.f, 0.f, 0.f, 0.f, 0.f, 0.f, 0.f};
    int i = beg;
    for (; i + 1 < end; i += 2) {
        int s0 = csrc[i];
        int s1 = csrc[i + 1];
        float p0 = __expf(lrelu(elp[s0 * NHD + head] + erh));
        float p1 = __expf(lrelu(elp[s1 * NHD + head] + erh));
        den += p0 + p1;
        const float4* z0p = (const float4*)(z + (size_t)s0 * HIDD + lane * 8);
        const float4* z1p = (const float4*)(z + (size_t)s1 * HIDD + lane * 8);
        float4 a0 = z0p[0], b0 = z0p[1];
        float4 a1 = z1p[0], b1 = z1p[1];
        msg[0] += p0 * a0.x + p1 * a1.x;
        msg[1] += p0 * a0.y + p1 * a1.y;
        msg[2] += p0 * a0.z + p1 * a1.z;
        msg[3] += p0 * a0.w + p1 * a1.w;
        msg[4] += p0 * b0.x + p1 * b1.x;
        msg[5] += p0 * b0.y + p1 * b1.y;
        msg[6] += p0 * b0.z + p1 * b1.z;
        msg[7] += p0 * b0.w + p1 * b1.w;
    }
    if (i < end) {
        int s = csrc[i];
        float p = __expf(lrelu(elp[s * NHD + head] + erh));
        den += p;
        const float4* zp = (const float4*)(z + (size_t)s * HIDD + lane * 8);
        float4 a = zp[0], b = zp[1];
        msg[0] += p * a.x; msg[1] += p * a.y; msg[2] += p * a.z; msg[3] += p * a.w;
        msg[4] += p * b.x; msg[5] += p * b.y; msg[6] += p * b.z; msg[7] += p * b.w;
    }
    float inv = 1.f / fmaxf(den, 1e-9f);
    const float4* bp = (const float4*)(bias + lane * 8);
    float4 b0 = bp[0], b1 = bp[1];
    float4 o0, o1;
    o0.x = fmaxf(msg[0] * inv + b0.x, 0.f);
    o0.y = fmaxf(msg[1] * inv + b0.y, 0.f);
    o0.z = fmaxf(msg[2] * inv + b0.z, 0.f);
    o0.w = fmaxf(msg[3] * inv + b0.w, 0.f);
    o1.x = fmaxf(msg[4] * inv + b1.x, 0.f);
    o1.y = fmaxf(msg[5] * inv + b1.y, 0.f);
    o1.z = fmaxf(msg[6] * inv + b1.z, 0.f);
    o1.w = fmaxf(msg[7] * inv + b1.w, 0.f);
    if (PACKED) {
        unsigned int hp[4], lp[4];
        split4(o0, hp, lp);
        split4(o1, hp + 2, lp + 2);
        *(uint4*)(pah + (size_t)warp * (HIDD / 2) + lane * 4) = make_uint4(hp[0], hp[1], hp[2], hp[3]);
        *(uint4*)(pal + (size_t)warp * (HIDD / 2) + lane * 4) = make_uint4(lp[0], lp[1], lp[2], lp[3]);
    } else {
        float4* op = (float4*)(hout + (size_t)warp * HIDD + lane * 8);
        op[0] = o0; op[1] = o1;
    }
}

// ---------------- fused GIN gather: edge-outer, 2-way unrolled --------------
// NCH chunks of 128 floats; chunk c covers cols [c*128, c*128+128).
// NCH==3: chunks 0..1 from hA (width 256), chunk 2 from hB (width 128).
template <int NCH>
__global__ __launch_bounds__(256)
void gin_gather_kernel(const int* __restrict__ csrc, const int* __restrict__ rowptr,
                       const float* __restrict__ hA, const float* __restrict__ hB,
                       const float* __restrict__ epsp,
                       unsigned int* __restrict__ ph, unsigned int* __restrict__ pl) {
    int warp = (blockIdx.x * blockDim.x + threadIdx.x) >> 5;
    if (warp >= NN) return;
    int lane = threadIdx.x & 31;
    int beg = rowptr[warp], end = rowptr[warp + 1];
    float e = 1.f + epsp[0];
    const int F = NCH * 128;
    const int lf = lane * 4;
    const int WA = (NCH < 3) ? F : HIDD;

    float4 a[NCH];
#pragma unroll
    for (int c = 0; c < NCH; c++) {
        int f = lf + c * 128;
        const float* base = (f < WA) ? (hA + (size_t)warp * WA + f)
                                     : (hB + (size_t)warp * FIN + (f - WA));
        float4 hv = *(const float4*)base;
        a[c] = make_float4(e * hv.x, e * hv.y, e * hv.z, e * hv.w);
    }
    int i = beg;
    for (; i + 1 < end; i += 2) {
        int s0 = csrc[i];
        int s1 = csrc[i + 1];
#pragma unroll
        for (int c = 0; c < NCH; c++) {
            int f = lf + c * 128;
            const float* b0 = (f < WA) ? (hA + (size_t)s0 * WA + f)
                                       : (hB + (size_t)s0 * FIN + (f - WA));
            const float* b1 = (f < WA) ? (hA + (size_t)s1 * WA + f)
                                       : (hB + (size_t)s1 * FIN + (f - WA));
            float4 v0 = *(const float4*)b0;
            float4 v1 = *(const float4*)b1;
            a[c].x += v0.x + v1.x; a[c].y += v0.y + v1.y;
            a[c].z += v0.z + v1.z; a[c].w += v0.w + v1.w;
        }
    }
    if (i < end) {
        int s = csrc[i];
#pragma unroll
        for (int c = 0; c < NCH; c++) {
            int f = lf + c * 128;
            const float* base = (f < WA) ? (hA + (size_t)s * WA + f)
                                         : (hB + (size_t)s * FIN + (f - WA));
            float4 v = *(const float4*)base;
            a[c].x += v.x; a[c].y += v.y; a[c].z += v.z; a[c].w += v.w;
        }
    }
#pragma unroll
    for (int c = 0; c < NCH; c++) {
        int f = lf + c * 128;
        unsigned int hp[2], lp[2];
        split4(a[c], hp, lp);
        *(uint2*)(ph + (size_t)warp * (F / 2) + (f >> 1)) = make_uint2(hp[0], hp[1]);
        *(uint2*)(pl + (size_t)warp * (F / 2) + (f >> 1)) = make_uint2(lp[0], lp[1]);
    }
}

// ---------------- BN finalize ------------------------------------------------
__global__ void bnfin_kernel(const float* __restrict__ g1, const float* __restrict__ be1,
                             const float* __restrict__ stats,
                             float* __restrict__ scale, float* __restrict__ shift) {
    int c = threadIdx.x;
    float inv = 1.f / (float)NN;
    float mu = stats[c] * inv;
    float var = stats[HIDD + c] * inv - mu * mu;
    float rstd = rsqrtf(var + 1e-5f);
    float sc = g1[c] * rstd;
    scale[c] = sc;
    shift[c] = be1[c] - mu * sc;
}

__global__ void zero_kernel(float* __restrict__ p, int n) {
    int idx = blockIdx.x * blockDim.x + threadIdx.x;
    int i4 = idx * 4;
    if (i4 >= n) return;
    *(float4*)(p + i4) = make_float4(0.f, 0.f, 0.f, 0.f);
}

// ---------------- host orchestration ---------------------------------------
static inline int blk4(int n) { return (n / 4 + 255) / 256; }
#define NODE_WARP_BLOCKS ((NN * 32 + 255) / 256)

struct TypeCtx {
    float *z, *h, *el, *er, *stats, *scale, *shift;
    unsigned int *pah, *pal;
    unsigned int *wh[NSLOT], *wl[NSLOT];
    int *cnt, *rowptr, *cur, *csrc, *bsum, *boff;
    cudaStream_t st, st2;
};

static void gemm(const TypeCtx& c, const unsigned int* AH, const unsigned int* AL,
                 int slot, const float* b, float* C, float* stats,
                 const float* alv, const float* arv, float* elp, float* erp,
                 int K, int relu, int ldc = HIDD, int coff = 0) {
    dim3 grid(HIDD / 128, (NN + 127) / 128);
    gemm_tc_kernel<<<grid, 256, GEMM_SMEM, c.st>>>(AH, AL, c.wh[slot], c.wl[slot],
                                                   b, C, stats, alv, arv, elp, erp,
                                                   NN, K / 2, ldc, coff, relu);
}

static void gemm_aff(const TypeCtx& c, const float* A, int slot, const float* b,
                     float* C, int K, int ldc = HIDD, int coff = 0) {
    dim3 grid(HIDD / 128, (NN + 127) / 128);
    gemm_aff_kernel<<<grid, 256, GEMM_AFF_SMEM, c.st>>>(A, c.scale, c.shift,
                                                        c.wh[slot], c.wl[slot],
                                                        b, C, NN, K / 2, ldc, coff);
}

extern "C" void kernel_launch(void* const* d_in, const int* in_sizes, int n_in,
                              void* d_out, int out_size) {
    const float* feats = (const float*)d_in[0];
    const int* src[2] = { (const int*)d_in[1], (const int*)d_in[3] };
    const int* dst[2] = { (const int*)d_in[2], (const int*)d_in[4] };
    const float* gat0_W   = (const float*)d_in[5];
    const float* gat0_al  = (const float*)d_in[6];
    const float* gat0_ar  = (const float*)d_in[7];
    const float* gat0_b   = (const float*)d_in[8];
    const float* gat1_W   = (const float*)d_in[9];
    const float* gat1_al  = (const float*)d_in[10];
    const float* gat1_ar  = (const float*)d_in[11];
    const float* gat1_b   = (const float*)d_in[12];
    const float* gin0_eps = (const float*)d_in[13];
    const float* gin0_W1  = (const float*)d_in[14];
    const float* gin0_b1  = (const float*)d_in[15];
    const float* gin0_g1  = (const float*)d_in[16];
    const float* gin0_be1 = (const float*)d_in[17];
    const float* gin0_W2  = (const float*)d_in[18];
    const float* gin0_b2  = (const float*)d_in[19];
    const float* gin1_eps = (const float*)d_in[20];
    const float* gin1_W1  = (const float*)d_in[21];
    const float* gin1_b1  = (const float*)d_in[22];
    const float* gin1_g1  = (const float*)d_in[23];
    const float* gin1_be1 = (const float*)d_in[24];
    const float* gin1_W2  = (const float*)d_in[25];
    const float* gin1_b2  = (const float*)d_in[26];
    float* out = (float*)d_out;

    float *zb, *hb, *elb, *erb, *stb, *scb, *shb;
    unsigned int *whb, *wlb, *pahb, *palb, *fh, *fl;
    int *cntb, *rpb, *curb, *csb, *bsb, *bob;
    cudaGetSymbolAddress((void**)&zb, g_z);
    cudaGetSymbolAddress((void**)&hb, g_h);
    cudaGetSymbolAddress((void**)&elb, g_el);
    cudaGetSymbolAddress((void**)&erb, g_er);
    cudaGetSymbolAddress((void**)&stb, g_stats);
    cudaGetSymbolAddress((void**)&scb, g_scale);
    cudaGetSymbolAddress((void**)&shb, g_shift);
    cudaGetSymbolAddress((void**)&whb, g_wh);
    cudaGetSymbolAddress((void**)&wlb, g_wl);
    cudaGetSymbolAddress((void**)&pahb, g_pah);
    cudaGetSymbolAddress((void**)&palb, g_pal);
    cudaGetSymbolAddress((void**)&fh, g_fh);
    cudaGetSymbolAddress((void**)&fl, g_fl);
    cudaGetSymbolAddress((void**)&cntb, g_cnt);
    cudaGetSymbolAddress((void**)&rpb, g_rowptr);
    cudaGetSymbolAddress((void**)&curb, g_cur);
    cudaGetSymbolAddress((void**)&csb, g_csrc);
    cudaGetSymbolAddress((void**)&bsb, g_bsum);
    cudaGetSymbolAddress((void**)&bob, g_boff);

    aconv_kernel<<<blk4(NN * FIN), 256>>>(feats, fh, fl, NN * FIN / 4);

    cudaEventRecord(g_si.e0, 0);
    for (int t = 0; t < TTYP; t++) {
        cudaStreamWaitEvent(g_si.s[t], g_si.e0, 0);
        cudaStreamWaitEvent(g_si.s2[t], g_si.e0, 0);
    }

    const float* Wsrc[TTYP][NSLOT];
    const int Wk[NSLOT] = { FIN, HIDD, CATF, HIDD, HIDD, HIDD };
    for (int t = 0; t < TTYP; t++) {
        Wsrc[t][0] = gat0_W + (size_t)t * FIN * HIDD;
        Wsrc[t][1] = gat1_W + (size_t)t * HIDD * HIDD;
        Wsrc[t][2] = gin0_W1 + (size_t)t * CATF * HIDD;
        Wsrc[t][3] = gin0_W2 + (size_t)t * HIDD * HIDD;
        Wsrc[t][4] = gin1_W1 + (size_t)t * HIDD * HIDD;
        Wsrc[t][5] = gin1_W2 + (size_t)t * HIDD * HIDD;
    }

    for (int t = 0; t < TTYP; t++) {
        TypeCtx c;
        c.z   = zb   + (size_t)t * NN * HIDD;
        c.h   = hb   + (size_t)t * NN * HIDD;
        c.el  = elb  + (size_t)t * NN * NHD;
        c.er  = erb  + (size_t)t * NN * NHD;
        c.stats = stb + (size_t)t * 2 * HIDD;
        c.scale = scb + (size_t)t * HIDD;
        c.shift = shb + (size_t)t * HIDD;
        for (int s = 0; s < NSLOT; s++) {
            c.wh[s] = whb + ((size_t)t * NSLOT + s) * HIDD * KWMAX;
            c.wl[s] = wlb + ((size_t)t * NSLOT + s) * HIDD * KWMAX;
        }
        c.pah = pahb + (size_t)t * NN * PKW;
        c.pal = palb + (size_t)t * NN * PKW;
        c.cnt = cntb + (size_t)t * NN;
        c.rowptr = rpb + (size_t)t * (NN + 1);
        c.cur = curb + (size_t)t * NN;
        c.csrc = csb + (size_t)t * NE;
        c.bsum = bsb + (size_t)t * SCB;
        c.boff = bob + (size_t)t * SCB;
        c.st  = g_si.s[t];
        c.st2 = g_si.s2[t];

        // ---- side stream: wconv slots 1-5 + CSR build ----
        for (int s = 1; s < NSLOT; s++) {
            int wtot = HIDD * (Wk[s] / 2);
            wconv_kernel<<<(wtot + 255) / 256, 256, 0, c.st2>>>(Wsrc[t][s], Wk[s],
                                                                c.wh[s], c.wl[s]);
        }
        zero_int_kernel<<<(NN + 255) / 256, 256, 0, c.st2>>>(c.cnt, NN);
        count_kernel<<<(NE + 255) / 256, 256, 0, c.st2>>>(dst[t], c.cnt);
        scan1_kernel<<<SCB, 256, 0, c.st2>>>(c.cnt, c.bsum);
        scan2_kernel<<<1, 256, 0, c.st2>>>(c.bsum, c.boff, c.rowptr);
        scan3_kernel<<<SCB, 256, 0, c.st2>>>(c.cnt, c.boff, c.rowptr, c.cur);
        fill_kernel<<<(NE + 255) / 256, 256, 0, c.st2>>>(src[t], dst[t], c.cur, c.csrc);
        cudaEventRecord(g_si.eC[t], c.st2);

        // ---- main stream ----
        {
            int wtot = HIDD * (Wk[0] / 2);
            wconv_kernel<<<(wtot + 255) / 256, 256, 0, c.st>>>(Wsrc[t][0], Wk[0],
                                                               c.wh[0], c.wl[0]);
        }
        // GAT layer 0: GEMM with fused el/er
        zero2_kernel<<<(NN * NHD / 4 + 255) / 256, 256, 0, c.st>>>(c.el, c.er, NN * NHD);
        gemm(c, fh, fl, 0, nullptr, c.z, nullptr,
             gat0_al + t * NHD * DH, gat0_ar + t * NHD * DH, c.el, c.er, FIN, 0);
        cudaStreamWaitEvent(c.st, g_si.eC[t], 0);
        gat_gather_kernel<1><<<NODE_WARP_BLOCKS, 256, 0, c.st>>>(
            c.csrc, c.rowptr, c.el, c.er, c.z, gat0_b + t * HIDD, nullptr, c.pah, c.pal);

        // GAT layer 1
        zero2_kernel<<<(NN * NHD / 4 + 255) / 256, 256, 0, c.st>>>(c.el, c.er, NN * NHD);
        gemm(c, c.pah, c.pal, 1, nullptr, c.z, nullptr,
             gat1_al + t * NHD * DH, gat1_ar + t * NHD * DH, c.el, c.er, HIDD, 0);
        gat_gather_kernel<0><<<NODE_WARP_BLOCKS, 256, 0, c.st>>>(
            c.csrc, c.rowptr, c.el, c.er, c.z, gat1_b + t * HIDD, c.h, nullptr, nullptr);

        // GIN layer 0 (F=384, implicit concat [h | feats])
        gin_gather_kernel<3><<<NODE_WARP_BLOCKS, 256, 0, c.st>>>(
            c.csrc, c.rowptr, c.h, feats, gin0_eps + t, c.pah, c.pal);
        zero_kernel<<<1, 128, 0, c.st>>>(c.stats, 2 * HIDD);
        gemm(c, c.pah, c.pal, 2, gin0_b1 + t * HIDD, c.z, c.stats,
             nullptr, nullptr, nullptr, nullptr, CATF, 0);
        bnfin_kernel<<<1, HIDD, 0, c.st>>>(gin0_g1 + t * HIDD, gin0_be1 + t * HIDD,
                                           c.stats, c.scale, c.shift);
        gemm_aff(c, c.z, 3, gin0_b2 + t * HIDD, c.h, HIDD);

        // GIN layer 1 (F=256)
        gin_gather_kernel<2><<<NODE_WARP_BLOCKS, 256, 0, c.st>>>(
            c.csrc, c.rowptr, c.h, nullptr, gin1_eps + t, c.pah, c.pal);
        zero_kernel<<<1, 128, 0, c.st>>>(c.stats, 2 * HIDD);
        gemm(c, c.pah, c.pal, 4, gin1_b1 + t * HIDD, c.z, c.stats,
             nullptr, nullptr, nullptr, nullptr, HIDD, 0);
        bnfin_kernel<<<1, HIDD, 0, c.st>>>(gin1_g1 + t * HIDD, gin1_be1 + t * HIDD,
                                           c.stats, c.scale, c.shift);
        gemm_aff(c, c.z, 5, gin1_b2 + t * HIDD, out, HIDD, TTYP * HIDD, t * HIDD);
    }

    cudaEventRecord(g_si.e1, g_si.s[0]);
    cudaEventRecord(g_si.e2, g_si.s[1]);
    cudaStreamWaitEvent((cudaStream_t)0, g_si.e1, 0);
    cudaStreamWaitEvent((cudaStream_t)0, g_si.e2, 0);
}